// round 5
// baseline (speedup 1.0000x reference)
#include <cuda_runtime.h>
#include <cuda_bf16.h>

#define SEQL 2048
#define BATCH 2
#define HIDD 1024
#define NH 16
#define DHD 64
#define NR 101

// Scratch (static __device__ — allocation-free per harness rules)
__device__ float g_Qp[BATCH*NH*SEQL*DHD];
__device__ float g_Kp[BATCH*NH*SEQL*DHD];
__device__ float g_Vp[BATCH*NH*SEQL*DHD];
__device__ float g_Ctx[BATCH*SEQL*HIDD];
// pre-rounded + k-pair-permuted copies
__device__ float g_Xq[SEQL*BATCH*HIDD];
__device__ float g_Xk[SEQL*BATCH*HIDD];
__device__ float g_Xv[SEQL*BATCH*HIDD];
__device__ float g_Wqp[HIDD*HIDD];
__device__ float g_Wkp[HIDD*HIDD];
__device__ float g_Wvp[HIDD*HIDD];
__device__ float g_Wop[HIDD*HIDD];

__device__ __forceinline__ unsigned f2tf(float f) {
    unsigned u;
    asm("cvt.rna.tf32.f32 %0, %1;" : "=r"(u) : "f"(f));
    return u;
}
__device__ __forceinline__ float f2tff(float f) { return __uint_as_float(f2tf(f)); }

__device__ __forceinline__ void mma_tf32(float* c, const unsigned* a, const unsigned* b) {
    asm volatile(
        "mma.sync.aligned.m16n8k8.row.col.f32.tf32.tf32.f32 "
        "{%0,%1,%2,%3}, {%4,%5,%6,%7}, {%8,%9}, {%0,%1,%2,%3};"
        : "+f"(c[0]), "+f"(c[1]), "+f"(c[2]), "+f"(c[3])
        : "r"(a[0]), "r"(a[1]), "r"(a[2]), "r"(a[3]), "r"(b[0]), "r"(b[1]));
}

// ---------------------------------------------------------------------------
// Pre-pass: round to tf32 and permute k within 8-groups as (0,4,1,5,2,6,3,7).
// z selects tensor: 0..2 X (524288 groups), 3..6 W (131072 groups).
// ---------------------------------------------------------------------------
__global__ __launch_bounds__(256) void preperm(
    const float* __restrict__ q, const float* __restrict__ k, const float* __restrict__ v,
    const float* __restrict__ wq, const float* __restrict__ wk,
    const float* __restrict__ wv, const float* __restrict__ wo,
    float* oq, float* ok, float* ov, float* owq, float* owk, float* owv, float* owo)
{
    const float* src; float* dst; int n8;
    switch (blockIdx.y) {
        case 0: src = q;  dst = oq;  n8 = SEQL*BATCH*HIDD/8; break;
        case 1: src = k;  dst = ok;  n8 = SEQL*BATCH*HIDD/8; break;
        case 2: src = v;  dst = ov;  n8 = SEQL*BATCH*HIDD/8; break;
        case 3: src = wq; dst = owq; n8 = HIDD*HIDD/8; break;
        case 4: src = wk; dst = owk; n8 = HIDD*HIDD/8; break;
        case 5: src = wv; dst = owv; n8 = HIDD*HIDD/8; break;
        default: src = wo; dst = owo; n8 = HIDD*HIDD/8; break;
    }
    int g = blockIdx.x * 256 + threadIdx.x;
    if (g >= n8) return;
    const float4* p = (const float4*)(src + (size_t)g * 8);
    float4 x = p[0], y = p[1];
    float4 o0 = make_float4(f2tff(x.x), f2tff(y.x), f2tff(x.y), f2tff(y.y));
    float4 o1 = make_float4(f2tff(x.z), f2tff(y.z), f2tff(x.w), f2tff(y.w));
    float4* d = (float4*)(dst + (size_t)g * 8);
    d[0] = o0; d[1] = o1;
}

// ---------------------------------------------------------------------------
// tf32 GEMM, inputs pre-rounded + pair-permuted. STS.128 fills, LDS.64 frags.
// MODE0: A in [L,B,HID] layout; out -> head layout [B,H,L,DH] (tf32-rounded;
//        D-permuted iff permqk). MODE1: A=[M,HID]; out seq-first fp32.
// ---------------------------------------------------------------------------
#define GEMM_BODY(MODE, PERMQK)                                                \
    __shared__ float As[2][128*24];                                            \
    __shared__ float Bs[2][128*24];                                            \
    const int tid  = threadIdx.x;                                              \
    const int lane = tid & 31, warp = tid >> 5;                                \
    const int grp = lane >> 2, l4 = lane & 3;                                  \
    const int wm = (warp >> 2) * 64;                                           \
    const int wn = (warp & 3) * 32;                                            \
    const int m0 = blockIdx.x * 128, n0 = blockIdx.y * 128;                    \
    float acc[4][4][4];                                                        \
    _Pragma("unroll")                                                          \
    for (int i = 0; i < 4; i++)                                                \
        _Pragma("unroll")                                                      \
        for (int j = 0; j < 4; j++)                                            \
            _Pragma("unroll")                                                  \
            for (int r = 0; r < 4; r++) acc[i][j][r] = 0.f;                    \
    const int r0 = tid >> 2, cc = (tid & 3) * 4;                               \
    const float *a0p, *a1p;                                                    \
    if (MODE == 0) {                                                           \
        int m = m0 + r0;      int b = m >> 11, l = m & 2047;                   \
        a0p = A + ((size_t)(l*BATCH+b))*HIDD + cc;                             \
        m = m0 + r0 + 64;     b = m >> 11;  l = m & 2047;                      \
        a1p = A + ((size_t)(l*BATCH+b))*HIDD + cc;                             \
    } else {                                                                   \
        a0p = A + (size_t)(m0+r0)*HIDD + cc;                                   \
        a1p = A + (size_t)(m0+r0+64)*HIDD + cc;                                \
    }                                                                          \
    const float* b0p = W + (size_t)(n0+r0)*HIDD + cc;                          \
    const float* b1p = W + (size_t)(n0+r0+64)*HIDD + cc;                       \
    float4 va0 = *(const float4*)a0p;                                          \
    float4 va1 = *(const float4*)a1p;                                          \
    float4 vb0 = *(const float4*)b0p;                                          \
    float4 vb1 = *(const float4*)b1p;                                          \
    auto sts = [&](int buf) {                                                  \
        *(float4*)&As[buf][r0*24+cc]      = va0;                               \
        *(float4*)&As[buf][(r0+64)*24+cc] = va1;                               \
        *(float4*)&Bs[buf][r0*24+cc]      = vb0;                               \
        *(float4*)&Bs[buf][(r0+64)*24+cc] = vb1;                               \
    };                                                                         \
    sts(0);                                                                    \
    __syncthreads();                                                           \
    int cur = 0;                                                               \
    for (int kt = 0; kt < 64; kt++) {                                          \
        if (kt + 1 < 64) {                                                     \
            int ko = (kt + 1) * 16;                                            \
            va0 = *(const float4*)(a0p + ko);                                  \
            va1 = *(const float4*)(a1p + ko);                                  \
            vb0 = *(const float4*)(b0p + ko);                                  \
            vb1 = *(const float4*)(b1p + ko);                                  \
        }                                                                      \
        const float* as = As[cur]; const float* bs = Bs[cur];                  \
        _Pragma("unroll")                                                      \
        for (int c = 0; c < 2; c++) {                                          \
            unsigned af[4][4], bf[4][2];                                       \
            _Pragma("unroll")                                                  \
            for (int i = 0; i < 4; i++) {                                      \
                int rr = wm + i*16 + grp;                                      \
                uint2 t0 = *(const uint2*)&as[rr*24 + c*8 + 2*l4];             \
                uint2 t1 = *(const uint2*)&as[(rr+8)*24 + c*8 + 2*l4];         \
                af[i][0] = t0.x; af[i][1] = t1.x;                              \
                af[i][2] = t0.y; af[i][3] = t1.y;                              \
            }                                                                  \
            _Pragma("unroll")                                                  \
            for (int j = 0; j < 4; j++) {                                      \
                int nn = wn + j*8 + grp;                                       \
                uint2 tb = *(const uint2*)&bs[nn*24 + c*8 + 2*l4];             \
                bf[j][0] = tb.x; bf[j][1] = tb.y;                              \
            }                                                                  \
            _Pragma("unroll")                                                  \
            for (int i = 0; i < 4; i++)                                        \
                _Pragma("unroll")                                              \
                for (int j = 0; j < 4; j++)                                    \
                    mma_tf32(acc[i][j], af[i], bf[j]);                         \
        }                                                                      \
        if (kt + 1 < 64) sts(cur ^ 1);                                         \
        __syncthreads();                                                       \
        cur ^= 1;                                                              \
    }                                                                          \
    const int pA = (l4 & 1) * 4 + (l4 >> 1);                                   \
    _Pragma("unroll")                                                          \
    for (int i = 0; i < 4; i++) {                                              \
        _Pragma("unroll")                                                      \
        for (int j = 0; j < 4; j++) {                                          \
            int cB = n0 + wn + j*8;                                            \
            int c0 = cB + l4*2;                                                \
            float bsv0 = bias[c0], bsv1 = bias[c0+1];                          \
            int d0, d1;                                                        \
            if (MODE == 0 && PERMQK) { d0 = cB + pA; d1 = cB + pA + 2; }       \
            else                     { d0 = c0;      d1 = c0 + 1;     }        \
            _Pragma("unroll")                                                  \
            for (int pr = 0; pr < 2; pr++) {                                   \
                int row = m0 + wm + i*16 + grp + pr*8;                         \
                int b = row >> 11, l = row & 2047;                             \
                float v0 = acc[i][j][pr*2+0] + bsv0;                           \
                float v1 = acc[i][j][pr*2+1] + bsv1;                           \
                if (MODE == 0) {                                               \
                    int h = c0 >> 6;                                           \
                    float* p = out + (((size_t)(b*NH+h))*SEQL + l)*DHD;        \
                    p[d0 & 63] = f2tff(v0);                                    \
                    p[d1 & 63] = f2tff(v1);                                    \
                } else {                                                       \
                    float* p = out + ((size_t)(l*BATCH+b))*HIDD;               \
                    p[d0] = v0; p[d1] = v1;                                    \
                }                                                              \
            }                                                                  \
        }                                                                      \
    }

// Fused Q/K/V projection: z selects projection; Q,K outputs D-permuted, V not.
__global__ __launch_bounds__(256) void gemm_qkv(
    const float* __restrict__ bq, const float* __restrict__ bk, const float* __restrict__ bv,
    float* oq, float* ok, float* ov)
{
    const float *A, *W, *bias; float* out; bool permqk;
    if (blockIdx.z == 0)      { A = g_Xq; W = g_Wqp; bias = bq; out = oq; permqk = true; }
    else if (blockIdx.z == 1) { A = g_Xk; W = g_Wkp; bias = bk; out = ok; permqk = true; }
    else                      { A = g_Xv; W = g_Wvp; bias = bv; out = ov; permqk = false; }
    GEMM_BODY(0, permqk)
}

__global__ __launch_bounds__(256) void gemm_out(
    const float* __restrict__ A, const float* __restrict__ W,
    const float* __restrict__ bias, float* __restrict__ out)
{
    GEMM_BODY(1, false)
}

// ---------------------------------------------------------------------------
// tf32 flash relative-attention, one-pass. 128 thr (4 warps), 64 q rows,
// k-tiles of 64, 3 blocks/SM. Q/K D-permuted (LDS.64 frags), P stored
// kl-permuted (LDS.64 A-frags). V row-major (scalar B-frags).
// ---------------------------------------------------------------------------
#define STK 72
#define OFFQ 0
#define OFFK 4608
#define OFFV 9216
#define OFFQD 13824                        // float offset of bf16 QD [64][104]
#define ATT_SMEM_BYTES 68608
#define C8 0.18033688011112042f            // 0.125 * log2(e)

__global__ __launch_bounds__(128, 3) void attn_tf32(
    const float* __restrict__ rel_k, const float* __restrict__ rel_v)
{
    extern __shared__ float sm[];
    const unsigned* smu = (const unsigned*)sm;
    __nv_bfloat16* qdp = (__nv_bfloat16*)(sm + OFFQD);
    __nv_bfloat16* pb  = (__nv_bfloat16*)sm;          // aliases dead Q region
    const int tid = threadIdx.x;
    const int lane = tid & 31, w = tid >> 5;
    const int grp = lane >> 2, l4 = lane & 3;
    const int bh = blockIdx.y;
    const int q0 = blockIdx.x * 64;
    const size_t base = (size_t)bh * SEQL * DHD;
    const int rl0 = w*16 + grp;
    const int pA = (l4 & 1) * 4 + (l4 >> 1);   // perm position of col l4*2

    // Q tile (pre-rounded + D-permuted floats — straight float4 copy)
    #pragma unroll
    for (int s = 0; s < 8; s++) {
        int i = tid + s*128; int r = i >> 4, c4 = (i & 15)*4;
        *(float4*)(sm + OFFQ + r*STK + c4) =
            *(const float4*)(g_Qp + base + (size_t)(q0+r)*DHD + c4);
    }
    // rel_k rows 0..103 (zero-pad 101..103), D-permuted scatter, stride STK
    #pragma unroll
    for (int s = 0; s < 13; s++) {
        int i = tid + s*128; int r = i >> 4, c4 = (i & 15)*4;
        float4 v = make_float4(0.f,0.f,0.f,0.f);
        if (r < NR) v = *(const float4*)(rel_k + r*DHD + c4);
        int g8 = c4 & ~7, o = (c4 & 4) ? 1 : 0;
        float* p = sm + OFFK + r*STK + g8 + o;
        p[0] = v.x; p[2] = v.y; p[4] = v.z; p[6] = v.w;
    }
    __syncthreads();

    // persistent Q fragments (LDS.64 pairs)
    unsigned qf[8][4];
    #pragma unroll
    for (int c = 0; c < 8; c++) {
        uint2 t0 = *(const uint2*)&smu[OFFQ + rl0*STK + c*8 + 2*l4];
        uint2 t1 = *(const uint2*)&smu[OFFQ + (rl0+8)*STK + c*8 + 2*l4];
        qf[c][0] = t0.x; qf[c][1] = t1.x; qf[c][2] = t0.y; qf[c][3] = t1.y;
    }
    // qdot[q][r] = Q . rel_k[r] via mma -> bf16 table
    #pragma unroll
    for (int j = 0; j < 13; j++) {
        float c4a[4] = {0.f,0.f,0.f,0.f};
        #pragma unroll
        for (int c = 0; c < 8; c++) {
            uint2 tb = *(const uint2*)&smu[OFFK + (j*8+grp)*STK + c*8 + 2*l4];
            unsigned bf[2] = {tb.x, tb.y};
            mma_tf32(c4a, qf[c], bf);
        }
        int col = j*8 + l4*2;
        *(__nv_bfloat162*)(qdp + rl0*104 + col)     = __floats2bfloat162_rn(c4a[0], c4a[1]);
        *(__nv_bfloat162*)(qdp + (rl0+8)*104 + col) = __floats2bfloat162_rn(c4a[2], c4a[3]);
    }
    __syncthreads();

    // zero band buffer (overwrites Q region; 64*100 bf16 = 3200 words)
    {
        unsigned* pbw = (unsigned*)pb;
        #pragma unroll
        for (int s = 0; s < 25; s++) pbw[tid + s*128] = 0u;
    }
    // per-row clip-bias constants (pre-scaled by C8)
    float qlC[2], qrC[2];
    #pragma unroll
    for (int hh = 0; hh < 2; hh++) {
        qlC[hh] = __bfloat162float(qdp[(rl0+hh*8)*104 + 0])   * C8;
        qrC[hh] = __bfloat162float(qdp[(rl0+hh*8)*104 + 100]) * C8;
    }
    __syncthreads();

    float oacc[8][4];
    #pragma unroll
    for (int j = 0; j < 8; j++)
        #pragma unroll
        for (int r = 0; r < 4; r++) oacc[j][r] = 0.f;
    float lft[2] = {0.f, 0.f}, rgt[2] = {0.f, 0.f};

    for (int k0 = 0; k0 < SEQL; k0 += 64) {
        // fill K,V tiles — raw float4 (K D-permuted by gemm; V plain)
        #pragma unroll
        for (int s = 0; s < 8; s++) {
            int i = tid + s*128; int r = i >> 4, c4 = (i & 15)*4;
            size_t g = base + (size_t)(k0+r)*DHD + c4;
            *(float4*)(sm + OFFK + r*STK + c4) = *(const float4*)(g_Kp + g);
            *(float4*)(sm + OFFV + r*STK + c4) = *(const float4*)(g_Vp + g);
        }
        __syncthreads();

        // S = Q K^T  (LDS.64 B-frags)
        float sfr[8][4];
        #pragma unroll
        for (int j = 0; j < 8; j++) {
            sfr[j][0]=sfr[j][1]=sfr[j][2]=sfr[j][3]=0.f;
            #pragma unroll
            for (int c = 0; c < 8; c++) {
                uint2 tb = *(const uint2*)&smu[OFFK + (j*8+grp)*STK + c*8 + 2*l4];
                unsigned bf[2] = {tb.x, tb.y};
                mma_tf32(sfr[j], qf[c], bf);
            }
        }
        __syncthreads();   // all warps done reading Ks before Ps overwrites

        const int dq = k0 - q0;
        if (dq == -64 || dq == 0 || dq == 64) {
            // ---- near tile: per-element clip index + band store ----
            #pragma unroll
            for (int j = 0; j < 8; j++) {
                #pragma unroll
                for (int hh = 0; hh < 2; hh++) {
                    int rl = rl0 + hh*8;
                    int col = j*8 + l4*2;
                    int dlt = k0 + col - (q0 + rl);
                    int ix0 = min(max(dlt, -50), 50) + 50;
                    int ix1 = min(max(dlt+1, -50), 50) + 50;
                    float qd0 = __bfloat162float(qdp[rl*104 + ix0]);
                    float qd1 = __bfloat162float(qdp[rl*104 + ix1]);
                    float p0 = exp2f((sfr[j][hh*2+0] + qd0) * C8);
                    float p1 = exp2f((sfr[j][hh*2+1] + qd1) * C8);
                    if (dlt <= -50)     lft[hh] += p0;
                    else if (dlt >= 50) rgt[hh] += p0;
                    else pb[rl*100 + dlt + 49] = __float2bfloat16(p0);
                    if (dlt+1 <= -50)     lft[hh] += p1;
                    else if (dlt+1 >= 50) rgt[hh] += p1;
                    else pb[rl*100 + dlt + 50] = __float2bfloat16(p1);
                    sm[OFFK + rl*STK + j*8 + pA]     = p0;   // kl-permuted P
                    sm[OFFK + rl*STK + j*8 + pA + 2] = p1;
                }
            }
        } else {
            // ---- far tile: constant clip bias per row ----
            const bool leftT = dq < 0;
            const float qc0 = leftT ? qlC[0] : qrC[0];
            const float qc1 = leftT ? qlC[1] : qrC[1];
            float ts[2] = {0.f, 0.f};
            #pragma unroll
            for (int j = 0; j < 8; j++) {
                float p0 = exp2f(fmaf(sfr[j][0], C8, qc0));
                float p1 = exp2f(fmaf(sfr[j][1], C8, qc0));
                float p2 = exp2f(fmaf(sfr[j][2], C8, qc1));
                float p3 = exp2f(fmaf(sfr[j][3], C8, qc1));
                ts[0] += p0 + p1;
                ts[1] += p2 + p3;
                sm[OFFK + rl0*STK + j*8 + pA]         = p0;
                sm[OFFK + rl0*STK + j*8 + pA + 2]     = p1;
                sm[OFFK + (rl0+8)*STK + j*8 + pA]     = p2;
                sm[OFFK + (rl0+8)*STK + j*8 + pA + 2] = p3;
            }
            if (leftT) { lft[0] += ts[0]; lft[1] += ts[1]; }
            else       { rgt[0] += ts[0]; rgt[1] += ts[1]; }
        }
        __syncwarp();

        // O += P V  (LDS.64 A-frags; V scalar B-frags conflict-free)
        #pragma unroll
        for (int c = 0; c < 8; c++) {
            uint2 t0 = *(const uint2*)&smu[OFFK + rl0*STK + c*8 + 2*l4];
            uint2 t1 = *(const uint2*)&smu[OFFK + (rl0+8)*STK + c*8 + 2*l4];
            unsigned af[4] = {t0.x, t1.x, t0.y, t1.y};
            #pragma unroll
            for (int j = 0; j < 8; j++) {
                unsigned bf[2];
                bf[0] = smu[OFFV + (c*8+l4)*STK + j*8 + grp];
                bf[1] = smu[OFFV + (c*8+l4+4)*STK + j*8 + grp];
                mma_tf32(oacc[j], af, bf);
            }
        }
        __syncthreads();
    }

    // reduce clip masses across quad
    #pragma unroll
    for (int hh = 0; hh < 2; hh++) {
        lft[hh] += __shfl_xor_sync(0xffffffffu, lft[hh], 1);
        lft[hh] += __shfl_xor_sync(0xffffffffu, lft[hh], 2);
        rgt[hh] += __shfl_xor_sync(0xffffffffu, rgt[hh], 1);
        rgt[hh] += __shfl_xor_sync(0xffffffffu, rgt[hh], 2);
    }

    // rel_v as plain float [101][64] into dead K/V region
    #pragma unroll
    for (int s = 0; s < 13; s++) {
        int i = tid + s*128;
        if (i < NR*16) {
            int r = i >> 4, c4 = (i & 15)*4;
            *(float4*)(sm + OFFK + r*64 + c4) = *(const float4*)(rel_v + r*DHD + c4);
        }
    }
    __syncthreads();

    // w2 = band . rel_v[1..99] + lft*rel_v[0] + rgt*rel_v[100]; band sum -> lsum
    float w2a[8][4];
    #pragma unroll
    for (int j = 0; j < 8; j++)
        #pragma unroll
        for (int r = 0; r < 4; r++) w2a[j][r] = 0.f;
    float bs0 = 0.f, bs1 = 0.f;
    for (int bnd = 0; bnd < 99; bnd++) {
        float pb0 = __bfloat162float(pb[rl0*100 + bnd]);
        float pb1 = __bfloat162float(pb[(rl0+8)*100 + bnd]);
        bs0 += pb0; bs1 += pb1;
        const float* rv = sm + OFFK + (bnd+1)*64 + l4*2;
        #pragma unroll
        for (int j = 0; j < 8; j++) {
            float r0v = rv[j*8], r1v = rv[j*8+1];
            w2a[j][0] += pb0*r0v; w2a[j][1] += pb0*r1v;
            w2a[j][2] += pb1*r0v; w2a[j][3] += pb1*r1v;
        }
    }
    {
        const float* rvL = sm + OFFK + 0*64 + l4*2;
        const float* rvR = sm + OFFK + 100*64 + l4*2;
        #pragma unroll
        for (int j = 0; j < 8; j++) {
            w2a[j][0] += lft[0]*rvL[j*8]   + rgt[0]*rvR[j*8];
            w2a[j][1] += lft[0]*rvL[j*8+1] + rgt[0]*rvR[j*8+1];
            w2a[j][2] += lft[1]*rvL[j*8]   + rgt[1]*rvR[j*8];
            w2a[j][3] += lft[1]*rvL[j*8+1] + rgt[1]*rvR[j*8+1];
        }
    }

    // Ctx written tf32-rounded + HID-pair-permuted (for gemm_out fast path)
    const int b = bh / NH, h = bh % NH;
    const float inv0 = 1.f / (lft[0] + rgt[0] + bs0);
    const float inv1 = 1.f / (lft[1] + rgt[1] + bs1);
    #pragma unroll
    for (int j = 0; j < 8; j++) {
        int cA = h*DHD + j*8 + pA;
        size_t o0 = ((size_t)(b*SEQL + q0 + rl0))*HIDD;
        size_t o1 = ((size_t)(b*SEQL + q0 + rl0 + 8))*HIDD;
        g_Ctx[o0 + cA]     = f2tff((oacc[j][0] + w2a[j][0]) * inv0);
        g_Ctx[o0 + cA + 2] = f2tff((oacc[j][1] + w2a[j][1]) * inv0);
        g_Ctx[o1 + cA]     = f2tff((oacc[j][2] + w2a[j][2]) * inv1);
        g_Ctx[o1 + cA + 2] = f2tff((oacc[j][3] + w2a[j][3]) * inv1);
    }
}

// ---------------------------------------------------------------------------
extern "C" void kernel_launch(void* const* d_in, const int* in_sizes, int n_in,
                              void* d_out, int out_size)
{
    const float* query = (const float*)d_in[0];
    const float* key   = (const float*)d_in[1];
    const float* value = (const float*)d_in[2];
    const float* Wq    = (const float*)d_in[3];
    const float* bq    = (const float*)d_in[4];
    const float* Wk    = (const float*)d_in[5];
    const float* bk    = (const float*)d_in[6];
    const float* Wv    = (const float*)d_in[7];
    const float* bv    = (const float*)d_in[8];
    const float* Wo    = (const float*)d_in[9];
    const float* bo    = (const float*)d_in[10];
    const float* rel_k = (const float*)d_in[11];
    const float* rel_v = (const float*)d_in[12];
    float* out = (float*)d_out;

    float *qp, *kp, *vp, *ctx, *xq, *xk, *xv, *wqp, *wkp, *wvp, *wop;
    cudaGetSymbolAddress((void**)&qp, g_Qp);
    cudaGetSymbolAddress((void**)&kp, g_Kp);
    cudaGetSymbolAddress((void**)&vp, g_Vp);
    cudaGetSymbolAddress((void**)&ctx, g_Ctx);
    cudaGetSymbolAddress((void**)&xq, g_Xq);
    cudaGetSymbolAddress((void**)&xk, g_Xk);
    cudaGetSymbolAddress((void**)&xv, g_Xv);
    cudaGetSymbolAddress((void**)&wqp, g_Wqp);
    cudaGetSymbolAddress((void**)&wkp, g_Wkp);
    cudaGetSymbolAddress((void**)&wvp, g_Wvp);
    cudaGetSymbolAddress((void**)&wop, g_Wop);

    dim3 gp((SEQL*BATCH*HIDD/8 + 255)/256, 7);
    preperm<<<gp, 256>>>(query, key, value, Wq, Wk, Wv, Wo,
                         xq, xk, xv, wqp, wkp, wvp, wop);

    dim3 gq(32, 8, 3);
    gemm_qkv<<<gq, 256>>>(bq, bk, bv, qp, kp, vp);

    cudaFuncSetAttribute(attn_tf32, cudaFuncAttributeMaxDynamicSharedMemorySize,
                         ATT_SMEM_BYTES);
    dim3 ga(SEQL / 64, BATCH * NH);
    attn_tf32<<<ga, 128, ATT_SMEM_BYTES>>>(rel_k, rel_v);

    dim3 gg(32, 8);
    gemm_out<<<gg, 256>>>(ctx, wop, bo, out);
}